// round 11
// baseline (speedup 1.0000x reference)
#include <cuda_runtime.h>
#include <cuda_fp16.h>
#include <math.h>

#define N 6400
#define L 21
#define HW 80
#define NSJ 10            // split-j chunks
#define JCH 640           // j per chunk
#define JS 64             // j per stage
#define NSTG (JCH / JS)   // 10
#define AW_BYTES 2048     // per-warp A stage: 16 rows x 128B (swizzled)
#define SMEM_BYTES (8 * AW_BYTES)   // 16 KB

// ---------------- device globals -------------------------------------------
static __device__ __align__(16) __half g_Kh[(size_t)N * N]; // 81.92 MB fp16 K
static __device__ float g_normbi[N];
static __device__ float g_normsp[N];
static __device__ float4 g_featA[N];
static __device__ float  g_featB[N];
static __device__ float  g_sqf[N];
static __device__ float  g_g1dT[HW * HW];
static __device__ float  g_Msp[L * L];
static __device__ float  g_Mbi[L * L];
static __device__ float  g_q[L * N];                     // fp32 planar (blur)
static __device__ __align__(16) __half g_qh24[24 * N];   // fp16, rows 21..23 = 0
static __device__ float  g_sp[L * N];
static __device__ float  g_acc[N * 24];                  // atomic accumulator [i*24+l]

// ---------------- asm helpers ----------------------------------------------
__device__ __forceinline__ unsigned smem_u32(const void* p) {
    return (unsigned)__cvta_generic_to_shared(p);
}
__device__ __forceinline__ void sts128(unsigned addr, uint4 v) {
    asm volatile("st.shared.v4.b32 [%0],{%1,%2,%3,%4};"
                 :: "r"(addr), "r"(v.x), "r"(v.y), "r"(v.z), "r"(v.w));
}
__device__ __forceinline__ void ldmx4(unsigned* r, unsigned addr) {
    asm volatile("ldmatrix.sync.aligned.m8n8.x4.shared.b16 {%0,%1,%2,%3},[%4];"
                 : "=r"(r[0]), "=r"(r[1]), "=r"(r[2]), "=r"(r[3]) : "r"(addr));
}
__device__ __forceinline__ void mma16816(float* c, const unsigned* a, unsigned b0, unsigned b1) {
    asm volatile("mma.sync.aligned.m16n8k16.row.col.f32.f16.f16.f32 "
                 "{%0,%1,%2,%3},{%4,%5,%6,%7},{%8,%9},{%0,%1,%2,%3};"
                 : "+f"(c[0]), "+f"(c[1]), "+f"(c[2]), "+f"(c[3])
                 : "r"(a[0]), "r"(a[1]), "r"(a[2]), "r"(a[3]), "r"(b0), "r"(b1));
}

// ---------------- setup: tables + softmax + folded mats + acc zero -----------
__global__ void k_init(const float* __restrict__ image, const float* __restrict__ logits,
                       const float* __restrict__ Wsp, const float* __restrict__ Wbi,
                       const float* __restrict__ C) {
    int gtid = blockIdx.x * 256 + threadIdx.x;
    if (gtid < N * 24) g_acc[gtid] = 0.0f;
    int i = gtid >> 5;
    int lane = threadIdx.x & 31;
    float v = (lane < L) ? logits[lane * N + i] : -1e30f;
    float m = v;
    #pragma unroll
    for (int off = 16; off > 0; off >>= 1)
        m = fmaxf(m, __shfl_xor_sync(0xffffffffu, m, off));
    float e = (lane < L) ? __expf(v - m) : 0.0f;
    float s = e;
    #pragma unroll
    for (int off = 16; off > 0; off >>= 1)
        s += __shfl_xor_sync(0xffffffffu, s, off);
    if (lane < L) {
        float qv = e / s;
        g_q[lane * N + i] = qv;
        g_qh24[lane * N + i] = __float2half_rn(qv);
    }
    int idx = gtid;
    if (idx < N) {
        g_qh24[21 * N + idx] = __float2half_rn(0.0f);
        g_qh24[22 * N + idx] = __float2half_rn(0.0f);
        g_qh24[23 * N + idx] = __float2half_rn(0.0f);
        int xp = idx / HW, xx = idx % HW;
        float d = (float)(xx - xp);
        g_g1dT[idx] = expf(-d * d / 18.0f);
        int x = idx % HW, y = idx / HW;
        float r = image[idx];
        float g = image[N + idx];
        float b = image[2 * N + idx];
        float4 fA;
        fA.x = (float)x / 160.0f;
        fA.y = (float)y / 160.0f;
        fA.z = r / 3.0f;
        fA.w = g / 3.0f;
        float fB = b / 3.0f;
        g_featA[idx] = fA;
        g_featB[idx] = fB;
        g_sqf[idx] = fA.x * fA.x + fA.y * fA.y + fA.z * fA.z + fA.w * fA.w + fB * fB;
        float Sx = 0.0f, Sy = 0.0f;
        for (int t = 0; t < HW; t++) {
            float dx = (float)(x - t);
            float dy = (float)(y - t);
            Sx += expf(-dx * dx / 18.0f);
            Sy += expf(-dy * dy / 18.0f);
        }
        g_normsp[idx] = 1.0f / (Sx * Sy + 1e-8f);
    }
    if (blockIdx.x == 800 - 1) {
        for (int t = threadIdx.x; t < L * L; t += 256) {
            int l = t / L, mm = t % L;
            float a = 0.0f, b = 0.0f;
            for (int k = 0; k < L; k++) {
                a += C[l * L + k] * Wsp[k * L + mm];
                b += C[l * L + k] * Wbi[k * L + mm];
            }
            g_Msp[t] = a;
            g_Mbi[t] = b;
        }
    }
}

// 8 rows per block, 2 j per thread iter: K_bi (fp16) + fp32 row sums
__global__ void __launch_bounds__(256) k_kbi() {
    __shared__ float red[8];
    int i0 = blockIdx.x * 8;
    if (threadIdx.x < 8) red[threadIdx.x] = 0.0f;
    float4 fa[8];
    float fb[8], sqi[8], sum[8];
    #pragma unroll
    for (int r = 0; r < 8; r++) {
        fa[r] = g_featA[i0 + r];
        fb[r] = g_featB[i0 + r];
        sqi[r] = g_sqf[i0 + r];
        sum[r] = 0.0f;
    }
    __syncthreads();
    for (int j = threadIdx.x * 2; j < N; j += 512) {
        float4 ga0 = g_featA[j], ga1 = g_featA[j + 1];
        float gb0 = g_featB[j], gb1 = g_featB[j + 1];
        float sq0 = g_sqf[j], sq1 = g_sqf[j + 1];
        #pragma unroll
        for (int r = 0; r < 8; r++) {
            float d0 = fa[r].x * ga0.x + fa[r].y * ga0.y + fa[r].z * ga0.z +
                       fa[r].w * ga0.w + fb[r] * gb0;
            float d1 = fa[r].x * ga1.x + fa[r].y * ga1.y + fa[r].z * ga1.z +
                       fa[r].w * ga1.w + fb[r] * gb1;
            float k0 = __expf(-0.5f * fmaxf(sqi[r] + sq0 - 2.0f * d0, 0.0f));
            float k1 = __expf(-0.5f * fmaxf(sqi[r] + sq1 - 2.0f * d1, 0.0f));
            *(__half2*)&g_Kh[(size_t)(i0 + r) * N + j] = __floats2half2_rn(k0, k1);
            sum[r] += k0 + k1;
        }
    }
    #pragma unroll
    for (int r = 0; r < 8; r++) {
        float s = sum[r];
        #pragma unroll
        for (int off = 16; off > 0; off >>= 1)
            s += __shfl_xor_sync(0xffffffffu, s, off);
        if ((threadIdx.x & 31) == 0) atomicAdd(&red[r], s);
    }
    __syncthreads();
    if (threadIdx.x < 8)
        g_normbi[i0 + threadIdx.x] = 1.0f / (red[threadIdx.x] + 1e-8f);
}

// ---------------- fused per-iteration: blur (blocks 0..20) + HMMA gemm -------
__global__ void __launch_bounds__(256) k_fused() {
    __shared__ __align__(16) unsigned char sraw[SMEM_BYTES + 25600];  // blur needs 25.6KB
    int t = threadIdx.x;

    if (blockIdx.x < L) {
        float* s = (float*)sraw;
        int l = blockIdx.x;
        float reg[25];
        #pragma unroll
        for (int k = 0; k < 25; k++) s[t + k * 256] = g_q[l * N + t + k * 256];
        __syncthreads();
        #pragma unroll
        for (int k = 0; k < 25; k++) {
            int flat = t + k * 256;
            int y = flat / HW, x = flat % HW;
            float acc = 0.0f;
            #pragma unroll 8
            for (int xp = 0; xp < HW; xp++)
                acc += g_g1dT[xp * HW + x] * s[y * HW + xp];
            reg[k] = acc;
        }
        __syncthreads();
        #pragma unroll
        for (int k = 0; k < 25; k++) s[t + k * 256] = reg[k];
        __syncthreads();
        #pragma unroll
        for (int k = 0; k < 25; k++) {
            int flat = t + k * 256;
            int y = flat / HW, x = flat % HW;
            float acc = 0.0f;
            #pragma unroll 8
            for (int yp = 0; yp < HW; yp++)
                acc += g_g1dT[yp * HW + y] * s[yp * HW + x];
            g_sp[l * N + flat] = acc;
        }
        return;
    }

    // ---- gemm block: D[i 128][l 24] over one 640-j chunk, no block barriers ----
    int g = blockIdx.x - L;
    int ib0 = (g / NSJ) * 128;
    int chunk = g % NSJ;
    int jc0 = chunk * JCH;
    int wid = t >> 5, lane = t & 31;
    unsigned sA = smem_u32(sraw) + wid * AW_BYTES;   // warp-private single buffer

    // reg-staged A fetch: 4 x LDG.128 per lane = 64B/lane in flight
    const __half* arow_base = g_Kh + (size_t)(ib0 + wid * 16) * N;
    uint4 rg[4];
    #define LOADG(sidx)                                                          \
        do {                                                                     \
            int jb = jc0 + (sidx) * JS;                                          \
            _Pragma("unroll")                                                    \
            for (int k = 0; k < 4; k++) {                                        \
                int idx = lane + k * 32;                                         \
                int row = idx >> 3, c16 = idx & 7;                               \
                rg[k] = *(const uint4*)(arow_base + (size_t)row * N + jb + c16 * 8); \
            }                                                                    \
        } while (0)

    LOADG(0);

    float acc[3][4];
    #pragma unroll
    for (int nt = 0; nt < 3; nt++)
        #pragma unroll
        for (int c = 0; c < 4; c++) acc[nt][c] = 0.0f;

    int arow = lane & 15;
    int ahalf = lane >> 4;
    // B fragment base: lane supplies {q[n][j+kp], q[n][j+kp+1]} with n=lane>>2, kp=(lane&3)*2
    const __half* qb = g_qh24 + (lane >> 2) * N + jc0 + (lane & 3) * 2;

    for (int stg = 0; stg < NSTG; stg++) {
        // store staged regs into warp buffer (swizzled), then make visible warp-wide
        #pragma unroll
        for (int k = 0; k < 4; k++) {
            int idx = lane + k * 32;
            int row = idx >> 3, c16 = idx & 7;
            sts128(sA + row * 128 + ((c16 ^ (row & 7)) * 16), rg[k]);
        }
        __syncwarp();
        if (stg + 1 < NSTG) LOADG(stg + 1);  // next stage in flight during compute
        int sj = stg * JS;
        #pragma unroll
        for (int ks = 0; ks < 4; ks++) {
            unsigned a[4];
            int col16 = ks * 2 + ahalf;
            ldmx4(a, sA + arow * 128 + ((col16 ^ (arow & 7)) * 16));
            #pragma unroll
            for (int nt = 0; nt < 3; nt++) {
                const __half* p = qb + nt * 8 * N + sj + ks * 16;
                unsigned b0 = *(const unsigned*)p;
                unsigned b1 = *(const unsigned*)(p + 8);
                mma16816(acc[nt], a, b0, b1);
            }
        }
        __syncwarp();  // all lanes done reading buffer before next overwrite
    }
    #undef LOADG

    // atomic accumulate: D[i][l] -> g_acc[i*24 + l]
    int i0 = ib0 + wid * 16 + (lane >> 2);
    int l0 = (lane & 3) * 2;
    #pragma unroll
    for (int nt = 0; nt < 3; nt++) {
        int l = nt * 8 + l0;
        atomicAdd(&g_acc[i0 * 24 + l], acc[nt][0]);
        atomicAdd(&g_acc[i0 * 24 + l + 1], acc[nt][1]);
        atomicAdd(&g_acc[(i0 + 8) * 24 + l], acc[nt][2]);
        atomicAdd(&g_acc[(i0 + 8) * 24 + l + 1], acc[nt][3]);
    }
}

// block-staged combine: 32 pixels/block, all global traffic coalesced
__global__ void __launch_bounds__(256) k_combine(const float* __restrict__ logits,
                                                 float* __restrict__ dout, int last) {
    __shared__ float msp[L * L], mbi[L * L];
    __shared__ float slog[L][32], ssp[L][32], sout[L][32];
    __shared__ float sacc[32 * 24];
    int t = threadIdx.x;
    int i0 = blockIdx.x * 32;

    for (int idx = t; idx < L * L; idx += 256) {
        msp[idx] = g_Msp[idx];
        mbi[idx] = g_Mbi[idx];
    }
    for (int idx = t; idx < L * 32; idx += 256) {
        int l = idx >> 5, c = idx & 31;
        slog[l][c] = logits[l * N + i0 + c];
        ssp[l][c] = g_sp[l * N + i0 + c] * g_normsp[i0 + c];
    }
    for (int idx = t; idx < 32 * 24; idx += 256) {
        sacc[idx] = g_acc[i0 * 24 + idx];
        g_acc[i0 * 24 + idx] = 0.0f;   // ready for next iteration
    }
    __syncthreads();

    int wid = t >> 5, lane = t & 31;
    for (int r = 0; r < 4; r++) {
        int c = wid * 4 + r;          // pixel within block
        float nbi = g_normbi[i0 + c];
        float cur = -1e30f;
        if (lane < L) {
            float a = 0.0f;
            #pragma unroll
            for (int m = 0; m < L; m++)
                a += msp[lane * L + m] * ssp[m][c] +
                     mbi[lane * L + m] * (sacc[c * 24 + m] * nbi);
            cur = slog[lane][c] + a;
        }
        if (last) {
            if (lane < L) sout[lane][c] = cur;
        } else {
            float m = cur;
            #pragma unroll
            for (int off = 16; off > 0; off >>= 1)
                m = fmaxf(m, __shfl_xor_sync(0xffffffffu, m, off));
            float e = (lane < L) ? __expf(cur - m) : 0.0f;
            float s = e;
            #pragma unroll
            for (int off = 16; off > 0; off >>= 1)
                s += __shfl_xor_sync(0xffffffffu, s, off);
            if (lane < L) sout[lane][c] = e / s;
        }
    }
    __syncthreads();

    if (last) {
        for (int idx = t; idx < L * 32; idx += 256) {
            int l = idx >> 5, c = idx & 31;
            dout[l * N + i0 + c] = sout[l][c];
        }
    } else {
        for (int idx = t; idx < L * 32; idx += 256) {
            int l = idx >> 5, c = idx & 31;
            float v = sout[l][c];
            g_q[l * N + i0 + c] = v;
            g_qh24[l * N + i0 + c] = __float2half_rn(v);
        }
    }
}

// ---------------- launch ------------------------------------------------------
extern "C" void kernel_launch(void* const* d_in, const int* in_sizes, int n_in,
                              void* d_out, int out_size) {
    const float* image = (const float*)d_in[0];
    const float* logits = (const float*)d_in[1];
    const float* Wsp = (const float*)d_in[2];
    const float* Wbi = (const float*)d_in[3];
    const float* C = (const float*)d_in[4];
    float* out = (float*)d_out;

    k_init<<<800, 256>>>(image, logits, Wsp, Wbi, C);
    k_kbi<<<N / 8, 256>>>();

    for (int it = 0; it < 5; it++) {
        k_fused<<<L + (N / 128) * NSJ, 256>>>();
        k_combine<<<200, 256>>>(logits, out, it == 4 ? 1 : 0);
    }
}

// round 13
// speedup vs baseline: 1.4168x; 1.4168x over previous
#include <cuda_runtime.h>
#include <cuda_fp16.h>
#include <math.h>

#define N 6400
#define L 21
#define HW 80
#define NSJ 10            // split-j chunks
#define JCH 640           // j per chunk
#define JS 32             // j per stage
#define NSTG (JCH / JS)   // 20
#define BSTR 648          // B smem row stride in halves (640 + 8 pad)
#define B_BYTES (24 * BSTR * 2)   // 31104
#define AW 1024           // per-warp A stage buffer: 16 rows x 64B (swizzled)
#define SMEM_BYTES (B_BYTES + 8 * 2 * AW)  // 47488 < 48KB static

// ---------------- device globals -------------------------------------------
static __device__ __align__(16) __half g_Kh[(size_t)N * N]; // 81.92 MB fp16 K
static __device__ float g_normbi[N];
static __device__ float g_normsp[N];
static __device__ float4 g_featA[N];
static __device__ float  g_featB[N];
static __device__ float  g_sqf[N];
static __device__ float  g_g1dT[HW * HW];
static __device__ float  g_Msp[L * L];
static __device__ float  g_Mbi[L * L];
static __device__ float  g_q[L * N];                     // fp32 planar (blur)
static __device__ __align__(16) __half g_qh24[24 * N];   // fp16, rows 21..23 = 0
static __device__ float  g_sp[L * N];
static __device__ float  g_acc[N * 24];                  // atomic accumulator [i*24+l]

// ---------------- asm helpers ----------------------------------------------
__device__ __forceinline__ unsigned smem_u32(const void* p) {
    return (unsigned)__cvta_generic_to_shared(p);
}
__device__ __forceinline__ void cpa16(unsigned dst, const void* src) {
    asm volatile("cp.async.cg.shared.global [%0],[%1],16;" :: "r"(dst), "l"(src));
}
__device__ __forceinline__ void cp_commit() {
    asm volatile("cp.async.commit_group;");
}
__device__ __forceinline__ void cp_wait0() { asm volatile("cp.async.wait_group 0;"); }
__device__ __forceinline__ void cp_wait1() { asm volatile("cp.async.wait_group 1;"); }
__device__ __forceinline__ void cp_wait2() { asm volatile("cp.async.wait_group 2;"); }
__device__ __forceinline__ void ldmx4(unsigned* r, unsigned addr) {
    asm volatile("ldmatrix.sync.aligned.m8n8.x4.shared.b16 {%0,%1,%2,%3},[%4];"
                 : "=r"(r[0]), "=r"(r[1]), "=r"(r[2]), "=r"(r[3]) : "r"(addr));
}
__device__ __forceinline__ void ldmx2(unsigned* r, unsigned addr) {
    asm volatile("ldmatrix.sync.aligned.m8n8.x2.shared.b16 {%0,%1},[%2];"
                 : "=r"(r[0]), "=r"(r[1]) : "r"(addr));
}
__device__ __forceinline__ void mma16816(float* c, const unsigned* a, unsigned b0, unsigned b1) {
    asm volatile("mma.sync.aligned.m16n8k16.row.col.f32.f16.f16.f32 "
                 "{%0,%1,%2,%3},{%4,%5,%6,%7},{%8,%9},{%0,%1,%2,%3};"
                 : "+f"(c[0]), "+f"(c[1]), "+f"(c[2]), "+f"(c[3])
                 : "r"(a[0]), "r"(a[1]), "r"(a[2]), "r"(a[3]), "r"(b0), "r"(b1));
}

// ---------------- setup: tables + softmax + folded mats + acc zero -----------
__global__ void k_init(const float* __restrict__ image, const float* __restrict__ logits,
                       const float* __restrict__ Wsp, const float* __restrict__ Wbi,
                       const float* __restrict__ C) {
    int gtid = blockIdx.x * 256 + threadIdx.x;
    if (gtid < N * 24) g_acc[gtid] = 0.0f;
    int i = gtid >> 5;
    int lane = threadIdx.x & 31;
    float v = (lane < L) ? logits[lane * N + i] : -1e30f;
    float m = v;
    #pragma unroll
    for (int off = 16; off > 0; off >>= 1)
        m = fmaxf(m, __shfl_xor_sync(0xffffffffu, m, off));
    float e = (lane < L) ? __expf(v - m) : 0.0f;
    float s = e;
    #pragma unroll
    for (int off = 16; off > 0; off >>= 1)
        s += __shfl_xor_sync(0xffffffffu, s, off);
    if (lane < L) {
        float qv = e / s;
        g_q[lane * N + i] = qv;
        g_qh24[lane * N + i] = __float2half_rn(qv);
    }
    int idx = gtid;
    if (idx < N) {
        g_qh24[21 * N + idx] = __float2half_rn(0.0f);
        g_qh24[22 * N + idx] = __float2half_rn(0.0f);
        g_qh24[23 * N + idx] = __float2half_rn(0.0f);
        int xp = idx / HW, xx = idx % HW;
        float d = (float)(xx - xp);
        g_g1dT[idx] = expf(-d * d / 18.0f);
        int x = idx % HW, y = idx / HW;
        float r = image[idx];
        float g = image[N + idx];
        float b = image[2 * N + idx];
        float4 fA;
        fA.x = (float)x / 160.0f;
        fA.y = (float)y / 160.0f;
        fA.z = r / 3.0f;
        fA.w = g / 3.0f;
        float fB = b / 3.0f;
        g_featA[idx] = fA;
        g_featB[idx] = fB;
        g_sqf[idx] = fA.x * fA.x + fA.y * fA.y + fA.z * fA.z + fA.w * fA.w + fB * fB;
        float Sx = 0.0f, Sy = 0.0f;
        for (int t = 0; t < HW; t++) {
            float dx = (float)(x - t);
            float dy = (float)(y - t);
            Sx += expf(-dx * dx / 18.0f);
            Sy += expf(-dy * dy / 18.0f);
        }
        g_normsp[idx] = 1.0f / (Sx * Sy + 1e-8f);
    }
    if (blockIdx.x == 800 - 1) {
        for (int t = threadIdx.x; t < L * L; t += 256) {
            int l = t / L, mm = t % L;
            float a = 0.0f, b = 0.0f;
            for (int k = 0; k < L; k++) {
                a += C[l * L + k] * Wsp[k * L + mm];
                b += C[l * L + k] * Wbi[k * L + mm];
            }
            g_Msp[t] = a;
            g_Mbi[t] = b;
        }
    }
}

// 8 rows per block, 2 j per thread iter: K_bi (fp16) + fp32 row sums
__global__ void __launch_bounds__(256) k_kbi() {
    __shared__ float red[8];
    int i0 = blockIdx.x * 8;
    if (threadIdx.x < 8) red[threadIdx.x] = 0.0f;
    float4 fa[8];
    float fb[8], sqi[8], sum[8];
    #pragma unroll
    for (int r = 0; r < 8; r++) {
        fa[r] = g_featA[i0 + r];
        fb[r] = g_featB[i0 + r];
        sqi[r] = g_sqf[i0 + r];
        sum[r] = 0.0f;
    }
    __syncthreads();
    for (int j = threadIdx.x * 2; j < N; j += 512) {
        float4 ga0 = g_featA[j], ga1 = g_featA[j + 1];
        float gb0 = g_featB[j], gb1 = g_featB[j + 1];
        float sq0 = g_sqf[j], sq1 = g_sqf[j + 1];
        #pragma unroll
        for (int r = 0; r < 8; r++) {
            float d0 = fa[r].x * ga0.x + fa[r].y * ga0.y + fa[r].z * ga0.z +
                       fa[r].w * ga0.w + fb[r] * gb0;
            float d1 = fa[r].x * ga1.x + fa[r].y * ga1.y + fa[r].z * ga1.z +
                       fa[r].w * ga1.w + fb[r] * gb1;
            float k0 = __expf(-0.5f * fmaxf(sqi[r] + sq0 - 2.0f * d0, 0.0f));
            float k1 = __expf(-0.5f * fmaxf(sqi[r] + sq1 - 2.0f * d1, 0.0f));
            *(__half2*)&g_Kh[(size_t)(i0 + r) * N + j] = __floats2half2_rn(k0, k1);
            sum[r] += k0 + k1;
        }
    }
    #pragma unroll
    for (int r = 0; r < 8; r++) {
        float s = sum[r];
        #pragma unroll
        for (int off = 16; off > 0; off >>= 1)
            s += __shfl_xor_sync(0xffffffffu, s, off);
        if ((threadIdx.x & 31) == 0) atomicAdd(&red[r], s);
    }
    __syncthreads();
    if (threadIdx.x < 8)
        g_normbi[i0 + threadIdx.x] = 1.0f / (red[threadIdx.x] + 1e-8f);
}

// ---------------- fused per-iteration: blur (blocks 0..20) + HMMA gemm -------
__global__ void __launch_bounds__(256) k_fused() {
    __shared__ __align__(16) unsigned char sraw[SMEM_BYTES];  // 47.5KB (blur uses 25.6)
    int t = threadIdx.x;

    if (blockIdx.x < L) {
        float* s = (float*)sraw;
        int l = blockIdx.x;
        float reg[25];
        #pragma unroll
        for (int k = 0; k < 25; k++) s[t + k * 256] = g_q[l * N + t + k * 256];
        __syncthreads();
        #pragma unroll
        for (int k = 0; k < 25; k++) {
            int flat = t + k * 256;
            int y = flat / HW, x = flat % HW;
            float acc = 0.0f;
            #pragma unroll 8
            for (int xp = 0; xp < HW; xp++)
                acc += g_g1dT[xp * HW + x] * s[y * HW + xp];
            reg[k] = acc;
        }
        __syncthreads();
        #pragma unroll
        for (int k = 0; k < 25; k++) s[t + k * 256] = reg[k];
        __syncthreads();
        #pragma unroll
        for (int k = 0; k < 25; k++) {
            int flat = t + k * 256;
            int y = flat / HW, x = flat % HW;
            float acc = 0.0f;
            #pragma unroll 8
            for (int yp = 0; yp < HW; yp++)
                acc += g_g1dT[yp * HW + y] * s[yp * HW + x];
            g_sp[l * N + flat] = acc;
        }
        return;
    }

    // ---- gemm block: D[i 128][l 24] over one 640-j chunk ----
    int g = blockIdx.x - L;
    int ib0 = (g / NSJ) * 128;
    int chunk = g % NSJ;
    int jc0 = chunk * JCH;
    int wid = t >> 5, lane = t & 31;
    unsigned sB = smem_u32(sraw);
    unsigned sA = sB + B_BYTES + wid * (2 * AW);  // warp-private double buffer

    // B fill: whole chunk q-tile [24][640], once
    #pragma unroll
    for (int k = 0; k < 8; k++) {
        int idx = t + k * 256;
        if (idx < 1920) {
            int row = idx / 80, c = idx % 80;
            cpa16(sB + (row * BSTR + c * 8) * 2, g_qh24 + row * N + jc0 + c * 8);
        }
    }
    cp_commit();  // group: B

    const __half* arow_base = g_Kh + (size_t)(ib0 + wid * 16) * N;
    // per-warp A stage fill: 16 rows x 32 halves (64B rows, swizzled 16B units)
    #define FILLA(sidx, buf)                                                     \
        do {                                                                     \
            int jb = jc0 + (sidx) * JS;                                          \
            _Pragma("unroll")                                                    \
            for (int k = 0; k < 2; k++) {                                        \
                int idx = lane + k * 32;                                         \
                int row = idx >> 2, c16 = idx & 3;                               \
                cpa16(sA + (buf) * AW + row * 64 +                               \
                          ((c16 ^ ((row >> 1) & 3)) * 16),                       \
                      arow_base + (size_t)row * N + jb + c16 * 8);               \
            }                                                                    \
            cp_commit();                                                         \
        } while (0)

    FILLA(0, 0);
    FILLA(1, 1);
    cp_wait2();        // B complete (A0, A1 may be pending)
    __syncthreads();   // B visible block-wide (only barrier)

    float acc[3][4];
    #pragma unroll
    for (int nt = 0; nt < 3; nt++)
        #pragma unroll
        for (int c = 0; c < 4; c++) acc[nt][c] = 0.0f;

    int arow = lane & 15;
    int ahalf = lane >> 4;
    int brow = lane & 7;
    int bk = ((lane >> 3) & 1) << 3;

    for (int stg = 0; stg < NSTG; stg++) {
        if (stg < NSTG - 1) cp_wait1(); else cp_wait0();  // A(stg) ready
        __syncwarp();
        unsigned Abuf = sA + (stg & 1) * AW;
        int sj = stg * JS;
        #pragma unroll
        for (int ks = 0; ks < 2; ks++) {
            unsigned a[4];
            int unit = ks * 2 + ahalf;
            ldmx4(a, Abuf + arow * 64 + ((unit ^ ((arow >> 1) & 3)) * 16));
            #pragma unroll
            for (int nt = 0; nt < 3; nt++) {
                unsigned b[2];
                ldmx2(b, sB + ((nt * 8 + brow) * BSTR + sj + ks * 16 + bk) * 2);
                mma16816(acc[nt], a, b[0], b[1]);
            }
        }
        __syncwarp();  // all lanes done with this buffer before refill
        if (stg + 2 < NSTG) FILLA(stg + 2, stg & 1);  // prefetch-ahead
    }
    #undef FILLA

    // atomic accumulate: D[i][l] -> g_acc[i*24 + l]
    int i0 = ib0 + wid * 16 + (lane >> 2);
    int l0 = (lane & 3) * 2;
    #pragma unroll
    for (int nt = 0; nt < 3; nt++) {
        int l = nt * 8 + l0;
        atomicAdd(&g_acc[i0 * 24 + l], acc[nt][0]);
        atomicAdd(&g_acc[i0 * 24 + l + 1], acc[nt][1]);
        atomicAdd(&g_acc[(i0 + 8) * 24 + l], acc[nt][2]);
        atomicAdd(&g_acc[(i0 + 8) * 24 + l + 1], acc[nt][3]);
    }
}

// warp-per-pixel: read+zero accumulator, norms, mix, add unary, fused softmax
__global__ void k_combine(const float* __restrict__ logits, float* __restrict__ dout,
                          int last) {
    __shared__ float msp[L * L], mbi[L * L];
    __shared__ float sv[8][L], bv[8][L];
    for (int idx = threadIdx.x; idx < L * L; idx += 256) {
        msp[idx] = g_Msp[idx];
        mbi[idx] = g_Mbi[idx];
    }
    __syncthreads();
    int wid = threadIdx.x >> 5;
    int lane = threadIdx.x & 31;
    int i = blockIdx.x * 8 + wid;

    if (lane < 24) {
        if (lane < L) {
            float s = g_sp[lane * N + i] * g_normsp[i];
            float b = g_acc[i * 24 + lane] * g_normbi[i];
            sv[wid][lane] = s;
            bv[wid][lane] = b;
        }
        g_acc[i * 24 + lane] = 0.0f;   // ready for next iteration's atomics
    }
    __syncwarp();

    float cur = -1e30f;
    if (lane < L) {
        float a = 0.0f;
        #pragma unroll
        for (int m = 0; m < L; m++)
            a += msp[lane * L + m] * sv[wid][m] + mbi[lane * L + m] * bv[wid][m];
        cur = logits[lane * N + i] + a;
    }
    if (last) {
        if (lane < L) dout[lane * N + i] = cur;
        return;
    }
    float m = cur;
    #pragma unroll
    for (int off = 16; off > 0; off >>= 1)
        m = fmaxf(m, __shfl_xor_sync(0xffffffffu, m, off));
    float e = (lane < L) ? __expf(cur - m) : 0.0f;
    float s = e;
    #pragma unroll
    for (int off = 16; off > 0; off >>= 1)
        s += __shfl_xor_sync(0xffffffffu, s, off);
    if (lane < L) {
        float qv = e / s;
        g_q[lane * N + i] = qv;
        g_qh24[lane * N + i] = __float2half_rn(qv);
    }
}

// ---------------- launch ------------------------------------------------------
extern "C" void kernel_launch(void* const* d_in, const int* in_sizes, int n_in,
                              void* d_out, int out_size) {
    const float* image = (const float*)d_in[0];
    const float* logits = (const float*)d_in[1];
    const float* Wsp = (const float*)d_in[2];
    const float* Wbi = (const float*)d_in[3];
    const float* C = (const float*)d_in[4];
    float* out = (float*)d_out;

    k_init<<<800, 256>>>(image, logits, Wsp, Wbi, C);
    k_kbi<<<N / 8, 256>>>();

    for (int it = 0; it < 5; it++) {
        k_fused<<<L + (N / 128) * NSJ, 256>>>();
        k_combine<<<800, 256>>>(logits, out, it == 4 ? 1 : 0);
    }
}

// round 14
// speedup vs baseline: 1.6665x; 1.1763x over previous
#include <cuda_runtime.h>
#include <cuda_fp16.h>
#include <math.h>

#define N 6400
#define L 21
#define HW 80
#define NSJ 10            // split-j chunks
#define JCH 640           // j per chunk
#define JS 32             // j per stage
#define NSTG (JCH / JS)   // 20
#define BSTR 648          // B smem row stride in halves (640 + 8 pad)
#define B_BYTES (24 * BSTR * 2)   // 31104
#define AW 1024           // per-warp A stage buffer: 16 rows x 64B (swizzled)
#define SMEM_BYTES (B_BYTES + 8 * 2 * AW)  // 47488 < 48KB static

// ---------------- device globals -------------------------------------------
static __device__ __align__(16) __half g_Kh[(size_t)N * N]; // 81.92 MB fp16 K
static __device__ float g_normbi[N];
static __device__ float g_normsp[N];
static __device__ float4 g_featA[N];
static __device__ float  g_featB[N];
static __device__ float  g_sqf[N];
static __device__ float  g_g1dT[HW * HW];
static __device__ float  g_Msp[L * L];
static __device__ float  g_Mbi[L * L];
static __device__ float  g_q[L * N];                     // fp32 planar (blur)
static __device__ __align__(16) __half g_qh24[24 * N];   // fp16, rows 21..23 = 0
static __device__ float  g_sp[L * N];
static __device__ float  g_acc[N * 24];                  // atomic accumulator [i*24+l]

// ---------------- asm helpers ----------------------------------------------
__device__ __forceinline__ unsigned smem_u32(const void* p) {
    return (unsigned)__cvta_generic_to_shared(p);
}
__device__ __forceinline__ void cpa16(unsigned dst, const void* src) {
    asm volatile("cp.async.cg.shared.global [%0],[%1],16;" :: "r"(dst), "l"(src));
}
__device__ __forceinline__ void cp_commit() {
    asm volatile("cp.async.commit_group;");
}
__device__ __forceinline__ void cp_wait0() { asm volatile("cp.async.wait_group 0;"); }
__device__ __forceinline__ void cp_wait1() { asm volatile("cp.async.wait_group 1;"); }
__device__ __forceinline__ void cp_wait2() { asm volatile("cp.async.wait_group 2;"); }
__device__ __forceinline__ void ldmx4(unsigned* r, unsigned addr) {
    asm volatile("ldmatrix.sync.aligned.m8n8.x4.shared.b16 {%0,%1,%2,%3},[%4];"
                 : "=r"(r[0]), "=r"(r[1]), "=r"(r[2]), "=r"(r[3]) : "r"(addr));
}
__device__ __forceinline__ void ldmx2(unsigned* r, unsigned addr) {
    asm volatile("ldmatrix.sync.aligned.m8n8.x2.shared.b16 {%0,%1},[%2];"
                 : "=r"(r[0]), "=r"(r[1]) : "r"(addr));
}
__device__ __forceinline__ void mma16816(float* c, const unsigned* a, unsigned b0, unsigned b1) {
    asm volatile("mma.sync.aligned.m16n8k16.row.col.f32.f16.f16.f32 "
                 "{%0,%1,%2,%3},{%4,%5,%6,%7},{%8,%9},{%0,%1,%2,%3};"
                 : "+f"(c[0]), "+f"(c[1]), "+f"(c[2]), "+f"(c[3])
                 : "r"(a[0]), "r"(a[1]), "r"(a[2]), "r"(a[3]), "r"(b0), "r"(b1));
}

// ---------------- setup: tables + softmax + acc zero -------------------------
__global__ void k_init(const float* __restrict__ image, const float* __restrict__ logits) {
    int gtid = blockIdx.x * 256 + threadIdx.x;
    if (gtid < N * 24) g_acc[gtid] = 0.0f;
    int i = gtid >> 5;
    int lane = threadIdx.x & 31;
    float v = (lane < L) ? logits[lane * N + i] : -1e30f;
    float m = v;
    #pragma unroll
    for (int off = 16; off > 0; off >>= 1)
        m = fmaxf(m, __shfl_xor_sync(0xffffffffu, m, off));
    float e = (lane < L) ? __expf(v - m) : 0.0f;
    float s = e;
    #pragma unroll
    for (int off = 16; off > 0; off >>= 1)
        s += __shfl_xor_sync(0xffffffffu, s, off);
    if (lane < L) {
        float qv = e / s;
        g_q[lane * N + i] = qv;
        g_qh24[lane * N + i] = __float2half_rn(qv);
    }
    int idx = gtid;
    if (idx < N) {
        g_qh24[21 * N + idx] = __float2half_rn(0.0f);
        g_qh24[22 * N + idx] = __float2half_rn(0.0f);
        g_qh24[23 * N + idx] = __float2half_rn(0.0f);
        int xp = idx / HW, xx = idx % HW;
        float d = (float)(xx - xp);
        g_g1dT[idx] = expf(-d * d / 18.0f);
        int x = idx % HW, y = idx / HW;
        float r = image[idx];
        float g = image[N + idx];
        float b = image[2 * N + idx];
        float4 fA;
        fA.x = (float)x / 160.0f;
        fA.y = (float)y / 160.0f;
        fA.z = r / 3.0f;
        fA.w = g / 3.0f;
        float fB = b / 3.0f;
        g_featA[idx] = fA;
        g_featB[idx] = fB;
        g_sqf[idx] = fA.x * fA.x + fA.y * fA.y + fA.z * fA.z + fA.w * fA.w + fB * fB;
        float Sx = 0.0f, Sy = 0.0f;
        for (int t = 0; t < HW; t++) {
            float dx = (float)(x - t);
            float dy = (float)(y - t);
            Sx += expf(-dx * dx / 18.0f);
            Sy += expf(-dy * dy / 18.0f);
        }
        g_normsp[idx] = 1.0f / (Sx * Sy + 1e-8f);
    }
}

// folded L x L mats — separate tiny launch (also shifts ncu capture to k_fused)
__global__ void k_prep(const float* __restrict__ Wsp, const float* __restrict__ Wbi,
                       const float* __restrict__ C) {
    for (int t = blockIdx.x * 256 + threadIdx.x; t < L * L; t += 512) {
        int l = t / L, mm = t % L;
        float a = 0.0f, b = 0.0f;
        for (int k = 0; k < L; k++) {
            a += C[l * L + k] * Wsp[k * L + mm];
            b += C[l * L + k] * Wbi[k * L + mm];
        }
        g_Msp[t] = a;
        g_Mbi[t] = b;
    }
}

// 8 rows per block, 2 j per thread iter: K_bi (fp16) + fp32 row sums
__global__ void __launch_bounds__(256) k_kbi() {
    __shared__ float red[8];
    int i0 = blockIdx.x * 8;
    if (threadIdx.x < 8) red[threadIdx.x] = 0.0f;
    float4 fa[8];
    float fb[8], sqi[8], sum[8];
    #pragma unroll
    for (int r = 0; r < 8; r++) {
        fa[r] = g_featA[i0 + r];
        fb[r] = g_featB[i0 + r];
        sqi[r] = g_sqf[i0 + r];
        sum[r] = 0.0f;
    }
    __syncthreads();
    for (int j = threadIdx.x * 2; j < N; j += 512) {
        float4 ga0 = g_featA[j], ga1 = g_featA[j + 1];
        float gb0 = g_featB[j], gb1 = g_featB[j + 1];
        float sq0 = g_sqf[j], sq1 = g_sqf[j + 1];
        #pragma unroll
        for (int r = 0; r < 8; r++) {
            float d0 = fa[r].x * ga0.x + fa[r].y * ga0.y + fa[r].z * ga0.z +
                       fa[r].w * ga0.w + fb[r] * gb0;
            float d1 = fa[r].x * ga1.x + fa[r].y * ga1.y + fa[r].z * ga1.z +
                       fa[r].w * ga1.w + fb[r] * gb1;
            float k0 = __expf(-0.5f * fmaxf(sqi[r] + sq0 - 2.0f * d0, 0.0f));
            float k1 = __expf(-0.5f * fmaxf(sqi[r] + sq1 - 2.0f * d1, 0.0f));
            *(__half2*)&g_Kh[(size_t)(i0 + r) * N + j] = __floats2half2_rn(k0, k1);
            sum[r] += k0 + k1;
        }
    }
    #pragma unroll
    for (int r = 0; r < 8; r++) {
        float s = sum[r];
        #pragma unroll
        for (int off = 16; off > 0; off >>= 1)
            s += __shfl_xor_sync(0xffffffffu, s, off);
        if ((threadIdx.x & 31) == 0) atomicAdd(&red[r], s);
    }
    __syncthreads();
    if (threadIdx.x < 8)
        g_normbi[i0 + threadIdx.x] = 1.0f / (red[threadIdx.x] + 1e-8f);
}

// ---------------- fused per-iteration: blur (blocks 0..20) + HMMA gemm -------
__global__ void __launch_bounds__(256) k_fused() {
    __shared__ __align__(16) unsigned char sraw[SMEM_BYTES];  // 47.5KB (blur uses 25.6)
    int t = threadIdx.x;

    if (blockIdx.x < L) {
        // spatial blur, 4 independent accumulators per pass (breaks RAW chain)
        float* s = (float*)sraw;
        int l = blockIdx.x;
        float reg[25];
        #pragma unroll
        for (int k = 0; k < 25; k++) s[t + k * 256] = g_q[l * N + t + k * 256];
        __syncthreads();
        #pragma unroll
        for (int k = 0; k < 25; k++) {
            int flat = t + k * 256;
            int y = flat / HW, x = flat % HW;
            float a0 = 0.0f, a1 = 0.0f, a2 = 0.0f, a3 = 0.0f;
            #pragma unroll 4
            for (int xp = 0; xp < HW; xp += 4) {
                a0 += g_g1dT[(xp + 0) * HW + x] * s[y * HW + xp + 0];
                a1 += g_g1dT[(xp + 1) * HW + x] * s[y * HW + xp + 1];
                a2 += g_g1dT[(xp + 2) * HW + x] * s[y * HW + xp + 2];
                a3 += g_g1dT[(xp + 3) * HW + x] * s[y * HW + xp + 3];
            }
            reg[k] = (a0 + a1) + (a2 + a3);
        }
        __syncthreads();
        #pragma unroll
        for (int k = 0; k < 25; k++) s[t + k * 256] = reg[k];
        __syncthreads();
        #pragma unroll
        for (int k = 0; k < 25; k++) {
            int flat = t + k * 256;
            int y = flat / HW, x = flat % HW;
            float a0 = 0.0f, a1 = 0.0f, a2 = 0.0f, a3 = 0.0f;
            #pragma unroll 4
            for (int yp = 0; yp < HW; yp += 4) {
                a0 += g_g1dT[(yp + 0) * HW + y] * s[(yp + 0) * HW + x];
                a1 += g_g1dT[(yp + 1) * HW + y] * s[(yp + 1) * HW + x];
                a2 += g_g1dT[(yp + 2) * HW + y] * s[(yp + 2) * HW + x];
                a3 += g_g1dT[(yp + 3) * HW + y] * s[(yp + 3) * HW + x];
            }
            g_sp[l * N + flat] = (a0 + a1) + (a2 + a3);
        }
        return;
    }

    // ---- gemm block: D[i 128][l 24] over one 640-j chunk ----
    int g = blockIdx.x - L;
    int ib0 = (g / NSJ) * 128;
    int chunk = g % NSJ;
    int jc0 = chunk * JCH;
    int wid = t >> 5, lane = t & 31;
    unsigned sB = smem_u32(sraw);
    unsigned sA = sB + B_BYTES + wid * (2 * AW);  // warp-private double buffer

    // B fill: whole chunk q-tile [24][640], once
    #pragma unroll
    for (int k = 0; k < 8; k++) {
        int idx = t + k * 256;
        if (idx < 1920) {
            int row = idx / 80, c = idx % 80;
            cpa16(sB + (row * BSTR + c * 8) * 2, g_qh24 + row * N + jc0 + c * 8);
        }
    }
    cp_commit();  // group: B

    const __half* arow_base = g_Kh + (size_t)(ib0 + wid * 16) * N;
    #define FILLA(sidx, buf)                                                     \
        do {                                                                     \
            int jb = jc0 + (sidx) * JS;                                          \
            _Pragma("unroll")                                                    \
            for (int k = 0; k < 2; k++) {                                        \
                int idx = lane + k * 32;                                         \
                int row = idx >> 2, c16 = idx & 3;                               \
                cpa16(sA + (buf) * AW + row * 64 +                               \
                          ((c16 ^ ((row >> 1) & 3)) * 16),                       \
                      arow_base + (size_t)row * N + jb + c16 * 8);               \
            }                                                                    \
            cp_commit();                                                         \
        } while (0)

    FILLA(0, 0);
    FILLA(1, 1);
    cp_wait2();        // B complete (A0, A1 may be pending)
    __syncthreads();   // B visible block-wide (only barrier)

    float acc[3][4];
    #pragma unroll
    for (int nt = 0; nt < 3; nt++)
        #pragma unroll
        for (int c = 0; c < 4; c++) acc[nt][c] = 0.0f;

    int arow = lane & 15;
    int ahalf = lane >> 4;
    int brow = lane & 7;
    int bk = ((lane >> 3) & 1) << 3;

    for (int stg = 0; stg < NSTG; stg++) {
        if (stg < NSTG - 1) cp_wait1(); else cp_wait0();  // A(stg) ready
        __syncwarp();
        unsigned Abuf = sA + (stg & 1) * AW;
        int sj = stg * JS;
        #pragma unroll
        for (int ks = 0; ks < 2; ks++) {
            unsigned a[4];
            int unit = ks * 2 + ahalf;
            ldmx4(a, Abuf + arow * 64 + ((unit ^ ((arow >> 1) & 3)) * 16));
            #pragma unroll
            for (int nt = 0; nt < 3; nt++) {
                unsigned b[2];
                ldmx2(b, sB + ((nt * 8 + brow) * BSTR + sj + ks * 16 + bk) * 2);
                mma16816(acc[nt], a, b[0], b[1]);
            }
        }
        __syncwarp();  // all lanes done with this buffer before refill
        if (stg + 2 < NSTG) FILLA(stg + 2, stg & 1);  // prefetch-ahead
    }
    #undef FILLA

    // atomic accumulate: D[i][l] -> g_acc[i*24 + l]
    int i0 = ib0 + wid * 16 + (lane >> 2);
    int l0 = (lane & 3) * 2;
    #pragma unroll
    for (int nt = 0; nt < 3; nt++) {
        int l = nt * 8 + l0;
        atomicAdd(&g_acc[i0 * 24 + l], acc[nt][0]);
        atomicAdd(&g_acc[i0 * 24 + l + 1], acc[nt][1]);
        atomicAdd(&g_acc[(i0 + 8) * 24 + l], acc[nt][2]);
        atomicAdd(&g_acc[(i0 + 8) * 24 + l + 1], acc[nt][3]);
    }
}

// warp-per-pixel: read+zero accumulator, norms, mix, add unary, fused softmax
__global__ void k_combine(const float* __restrict__ logits, float* __restrict__ dout,
                          int last) {
    __shared__ float msp[L * L], mbi[L * L];
    __shared__ float sv[8][L], bv[8][L];
    for (int idx = threadIdx.x; idx < L * L; idx += 256) {
        msp[idx] = g_Msp[idx];
        mbi[idx] = g_Mbi[idx];
    }
    __syncthreads();
    int wid = threadIdx.x >> 5;
    int lane = threadIdx.x & 31;
    int i = blockIdx.x * 8 + wid;

    if (lane < 24) {
        if (lane < L) {
            float s = g_sp[lane * N + i] * g_normsp[i];
            float b = g_acc[i * 24 + lane] * g_normbi[i];
            sv[wid][lane] = s;
            bv[wid][lane] = b;
        }
        g_acc[i * 24 + lane] = 0.0f;   // ready for next iteration's atomics
    }
    __syncwarp();

    float cur = -1e30f;
    if (lane < L) {
        float a = 0.0f;
        #pragma unroll
        for (int m = 0; m < L; m++)
            a += msp[lane * L + m] * sv[wid][m] + mbi[lane * L + m] * bv[wid][m];
        cur = logits[lane * N + i] + a;
    }
    if (last) {
        if (lane < L) dout[lane * N + i] = cur;
        return;
    }
    float m = cur;
    #pragma unroll
    for (int off = 16; off > 0; off >>= 1)
        m = fmaxf(m, __shfl_xor_sync(0xffffffffu, m, off));
    float e = (lane < L) ? __expf(cur - m) : 0.0f;
    float s = e;
    #pragma unroll
    for (int off = 16; off > 0; off >>= 1)
        s += __shfl_xor_sync(0xffffffffu, s, off);
    if (lane < L) {
        float qv = e / s;
        g_q[lane * N + i] = qv;
        g_qh24[lane * N + i] = __float2half_rn(qv);
    }
}

// ---------------- launch ------------------------------------------------------
extern "C" void kernel_launch(void* const* d_in, const int* in_sizes, int n_in,
                              void* d_out, int out_size) {
    const float* image = (const float*)d_in[0];
    const float* logits = (const float*)d_in[1];
    const float* Wsp = (const float*)d_in[2];
    const float* Wbi = (const float*)d_in[3];
    const float* C = (const float*)d_in[4];
    float* out = (float*)d_out;

    k_init<<<800, 256>>>(image, logits);
    k_prep<<<2, 256>>>(Wsp, Wbi, C);
    k_kbi<<<N / 8, 256>>>();

    for (int it = 0; it < 5; it++) {
        k_fused<<<L + (N / 128) * NSJ, 256>>>();
        k_combine<<<800, 256>>>(logits, out, it == 4 ? 1 : 0);
    }
}